// round 6
// baseline (speedup 1.0000x reference)
#include <cuda_runtime.h>
#include <cstdint>
#include <math.h>

// ============================================================================
// AdaptiveOutlierLoss: mean(relu(margin - min_c d_poincare(z_b, p_c)))
// B=32768, C=2048, D=512. arccosh monotone + (1-|x|^2) row-constant =>
// argmin_c d == argmin_c (x2 + y2 - 2 dot) / (1 - y2).
// INT8 warp-MMA (m16n8k32 s8s8s32) GEMM with fused min epilogue. Inputs
// quantized x320 (|elem| <= ~0.2 => no saturation); norms stay exact fp32;
// s32 accumulate exact; epilogue rescales dot by 1/320^2.
// ============================================================================

#define DDIM 512
#define MAXB 32768
#define MAXC 2048
#define QSCALE 320.0f
#define INV_2S2 1.953125e-5f   // 2 / (320*320)

// ---------------- device scratch ----------------
__device__ __align__(128) unsigned char g_zt[(size_t)MAXB * DDIM];  // s8 z (x320)
__device__ __align__(128) unsigned char g_pt[(size_t)MAXC * DDIM];  // s8 protos (x320)
__device__ float  g_x2[MAXB];
__device__ float2 g_pc[MAXC];        // (y2, 1/(1-y2)) per prototype
__device__ float  g_tmin[MAXB];
__device__ float  g_partial[MAXB / 128];

// ---------------- SMEM map ----------------
// A: 8 k-chunks x [128 rows x 80B]  (64 s8 k = 64B data + 16B pad)
// B: 4 stages  x [128 rows x 80B]
#define SM_A      0
#define SM_B      81920
#define SM_MIN    122880
#define SMEM_MAIN 123392

// ---------------- asm helpers ----------------
__device__ __forceinline__ uint32_t smem_u32(const void* p) {
    uint32_t a;
    asm("{ .reg .u64 t; cvta.to.shared.u64 t, %1; cvt.u32.u64 %0, t; }" : "=r"(a) : "l"(p));
    return a;
}
__device__ __forceinline__ void cp16(uint32_t dst, const void* src) {
    asm volatile("cp.async.cg.shared.global [%0], [%1], 16;" :: "r"(dst), "l"(src) : "memory");
}
__device__ __forceinline__ void cp_commit() {
    asm volatile("cp.async.commit_group;" ::: "memory");
}
template <int N>
__device__ __forceinline__ void cp_wait() {
    asm volatile("cp.async.wait_group %0;" :: "n"(N) : "memory");
}
#define LDSM4(r, addr)                                                           \
    asm volatile("ldmatrix.sync.aligned.m8n8.x4.shared.b16 {%0,%1,%2,%3}, [%4];" \
                 : "=r"((r)[0]), "=r"((r)[1]), "=r"((r)[2]), "=r"((r)[3])        \
                 : "r"(addr))
__device__ __forceinline__ void mma_s8(int* d, const uint32_t* a,
                                       uint32_t b0, uint32_t b1) {
    asm volatile(
        "mma.sync.aligned.m16n8k32.row.col.s32.s8.s8.s32 "
        "{%0,%1,%2,%3}, {%4,%5,%6,%7}, {%8,%9}, {%0,%1,%2,%3};"
        : "+r"(d[0]), "+r"(d[1]), "+r"(d[2]), "+r"(d[3])
        : "r"(a[0]), "r"(a[1]), "r"(a[2]), "r"(a[3]), "r"(b0), "r"(b1));
}

// fp32x4 -> 4 packed s8 bytes, scaled x320 (|v|*320 <= ~70, no clamping needed,
// but & 0xFF keeps the byte lanes clean for negatives)
__device__ __forceinline__ uint32_t pack4_s8(float4 v) {
    uint32_t a = (uint32_t)__float2int_rn(v.x * QSCALE) & 0xFFu;
    uint32_t b = (uint32_t)__float2int_rn(v.y * QSCALE) & 0xFFu;
    uint32_t c = (uint32_t)__float2int_rn(v.z * QSCALE) & 0xFFu;
    uint32_t d = (uint32_t)__float2int_rn(v.w * QSCALE) & 0xFFu;
    return a | (b << 8) | (c << 16) | (d << 24);
}

// ============================================================================
// Conversion: fp32 -> s8 row-major (x320), fused fp32 squared-norm.
// One warp per row.
// ============================================================================
__global__ void conv_z_kernel(const float* __restrict__ z, int B) {
    int w    = (blockIdx.x * blockDim.x + threadIdx.x) >> 5;
    int lane = threadIdx.x & 31;
    if (w >= B) return;
    const float* row = z + (size_t)w * DDIM;
    float s = 0.f;
    #pragma unroll
    for (int i = 0; i < 4; i++) {
        int f = i * 32 + lane;                 // float4 index
        float4 v = *(const float4*)(row + f * 4);
        s = fmaf(v.x, v.x, fmaf(v.y, v.y, fmaf(v.z, v.z, fmaf(v.w, v.w, s))));
        *(uint32_t*)(g_zt + (size_t)w * DDIM + f * 4) = pack4_s8(v);
    }
    #pragma unroll
    for (int o = 16; o; o >>= 1) s += __shfl_xor_sync(0xffffffffu, s, o);
    if (lane == 0) g_x2[w] = s;
}

__global__ void conv_p_kernel(const float* __restrict__ p, int C) {
    int w    = (blockIdx.x * blockDim.x + threadIdx.x) >> 5;
    int lane = threadIdx.x & 31;
    if (w >= C) return;
    const float* row = p + (size_t)w * DDIM;
    float s = 0.f;
    #pragma unroll
    for (int i = 0; i < 4; i++) {
        int f = i * 32 + lane;
        float4 v = *(const float4*)(row + f * 4);
        s = fmaf(v.x, v.x, fmaf(v.y, v.y, fmaf(v.z, v.z, fmaf(v.w, v.w, s))));
        *(uint32_t*)(g_pt + (size_t)w * DDIM + f * 4) = pack4_s8(v);
    }
    #pragma unroll
    for (int o = 16; o; o >>= 1) s += __shfl_xor_sync(0xffffffffu, s, o);
    if (lane == 0) g_pc[w] = make_float2(s, 1.0f / (1.0f - s));
}

// ============================================================================
// Main kernel: 1 CTA per 128 z-rows. A (128x512 s8) resident in SMEM at
// pitch 80 (ldmatrix conflict-free). B = 128 protos x 64 k per stage,
// 4-stage cp.async pipeline. 8 warps, warp tile 64(m)x32(n),
// m16n8k32 s8 -> s32; per-N-block min folded in registers.
// ============================================================================
__global__ void __launch_bounds__(256, 1)
min_dist_mma_kernel(int C) {
    extern __shared__ char smem[];
    const uint32_t sb   = smem_u32(smem);
    const int tid  = threadIdx.x;
    const int lane = tid & 31;
    const int wid  = tid >> 5;
    const int wm   = wid & 1;     // m block of 64
    const int wn   = wid >> 1;    // n block of 32
    const int mb   = blockIdx.x;
    const int NB   = C >> 7;      // 128-proto blocks
    const int NQ   = NB * 8;      // stages (64 k each)

    int* sMin = (int*)(smem + SM_MIN);
    if (tid < 128) sMin[tid] = 0x7F800000;

    // ---- prologue: A (whole 128x512B slice) + first 3 B stages ----
    {
        const char* abase = (const char*)g_zt + (size_t)mb * 65536;
        #pragma unroll 4
        for (int t = 0; t < 16; t++) {
            int i = tid + t * 256;          // 4096 16B chunks
            int r = i >> 5;                 // row 0..127 (32 chunks per row)
            int j = i & 31;                 // chunk within row: kchunk = j>>2
            cp16(sb + SM_A + (j >> 2) * 10240 + r * 80 + (j & 3) * 16,
                 abase + r * 512 + j * 16);
        }
    }
    auto load_B = [&](int s, int q) {
        int nb = q >> 3, kc = q & 7;
        const char* bbase = (const char*)g_pt + (size_t)nb * 65536 + kc * 64;
        #pragma unroll
        for (int t = 0; t < 2; t++) {
            int i = tid + t * 256;          // 512 chunks (128 rows x 4)
            int r = i >> 2, slot = i & 3;
            cp16(sb + SM_B + s * 10240 + r * 80 + slot * 16,
                 bbase + r * 512 + slot * 16);
        }
    };
    load_B(0, 0); cp_commit();              // group0 = A + B0
    load_B(1, 1); cp_commit();
    load_B(2, 2); cp_commit();

    // ---- per-thread constants ----
    const int g = lane >> 2;
    float x2r[8];
    #pragma unroll
    for (int mt = 0; mt < 4; mt++) {
        int r0 = mb * 128 + wm * 64 + mt * 16 + g;
        x2r[mt * 2]     = g_x2[r0];
        x2r[mt * 2 + 1] = g_x2[r0 + 8];
    }
    float rm[8];
    #pragma unroll
    for (int i = 0; i < 8; i++) rm[i] = __int_as_float(0x7F800000);

    int acc[4][4][4];
    #pragma unroll
    for (int mt = 0; mt < 4; mt++)
        #pragma unroll
        for (int nt = 0; nt < 4; nt++)
            #pragma unroll
            for (int k = 0; k < 4; k++) acc[mt][nt][k] = 0;

    const uint32_t aoff = sb + SM_A + (wm * 64 + (lane & 15)) * 80 + (lane >> 4) * 16;
    const uint32_t boff = sb + SM_B + (wn * 32 + (lane & 15)) * 80 + (lane >> 4) * 16;

    #pragma unroll 1
    for (int q = 0; q < NQ; q++) {
        const int s  = q & 3;
        const int kc = q & 7;
        const int nb = q >> 3;
        const int rem = NQ - 1 - q;
        if (rem >= 2)      cp_wait<2>();
        else if (rem == 1) cp_wait<1>();
        else               cp_wait<0>();
        __syncthreads();
        if (q + 3 < NQ) { load_B((q + 3) & 3, q + 3); cp_commit(); }

        // fragments: each ldsm x4 = 16 rows x 32 s8 k (one full k32 fragment)
        uint32_t afr[4][2][4];
        uint32_t bfr[2][2][4];
        #pragma unroll
        for (int mt = 0; mt < 4; mt++)
            #pragma unroll
            for (int ks = 0; ks < 2; ks++)
                LDSM4(afr[mt][ks], aoff + kc * 10240 + mt * 1280 + ks * 32);
        #pragma unroll
        for (int p = 0; p < 2; p++)
            #pragma unroll
            for (int ks = 0; ks < 2; ks++)
                LDSM4(bfr[p][ks], boff + s * 10240 + p * 1280 + ks * 32);

        #pragma unroll
        for (int ks = 0; ks < 2; ks++)
            #pragma unroll
            for (int mt = 0; mt < 4; mt++)
                #pragma unroll
                for (int nt = 0; nt < 4; nt++) {
                    int p = nt >> 1, sd = nt & 1;
                    mma_s8(acc[mt][nt], afr[mt][ks],
                           bfr[p][ks][sd], bfr[p][ks][sd + 2]);
                }

        if (kc == 7) {
            // epilogue for this 128-proto block: acc holds 320^2 * dot
            const int colbase = nb * 128 + wn * 32 + (lane & 3) * 2;
            #pragma unroll
            for (int nt = 0; nt < 4; nt++) {
                float2 pa = __ldg(&g_pc[colbase + nt * 8]);
                float2 pb = __ldg(&g_pc[colbase + nt * 8 + 1]);
                #pragma unroll
                for (int mt = 0; mt < 4; mt++) {
                    float v00 = fmaf(-INV_2S2, (float)acc[mt][nt][0], x2r[mt*2]   + pa.x) * pa.y;
                    float v01 = fmaf(-INV_2S2, (float)acc[mt][nt][1], x2r[mt*2]   + pb.x) * pb.y;
                    float v10 = fmaf(-INV_2S2, (float)acc[mt][nt][2], x2r[mt*2+1] + pa.x) * pa.y;
                    float v11 = fmaf(-INV_2S2, (float)acc[mt][nt][3], x2r[mt*2+1] + pb.x) * pb.y;
                    rm[mt*2]   = fminf(rm[mt*2],   fminf(v00, v01));
                    rm[mt*2+1] = fminf(rm[mt*2+1], fminf(v10, v11));
                    acc[mt][nt][0] = 0; acc[mt][nt][1] = 0;
                    acc[mt][nt][2] = 0; acc[mt][nt][3] = 0;
                }
            }
        }
    }

    // ---- cross-warp min + writeback (values >= 0 => int-bit order) ----
    __syncthreads();
    #pragma unroll
    for (int mt = 0; mt < 4; mt++) {
        atomicMin(&sMin[wm * 64 + mt * 16 + g],     __float_as_int(rm[mt*2]));
        atomicMin(&sMin[wm * 64 + mt * 16 + g + 8], __float_as_int(rm[mt*2+1]));
    }
    __syncthreads();
    if (tid < 128) g_tmin[mb * 128 + tid] = __int_as_float(sMin[tid]);
}

// ============================================================================
// Finalize: deterministic two-stage reduction.
// ============================================================================
__global__ void fin1_kernel(const float* __restrict__ margin_p) {
    __shared__ float red[4];
    const int r = blockIdx.x * 128 + threadIdx.x;
    const float margin = *margin_p;
    float t   = g_tmin[r];
    float x2  = g_x2[r];
    float arg = fmaxf(1.0f + 2.0f * t / (1.0f - x2), 1.0f + 1e-7f);
    float v   = fmaxf(margin - acoshf(arg), 0.0f);
    #pragma unroll
    for (int o = 16; o; o >>= 1) v += __shfl_xor_sync(0xffffffffu, v, o);
    if ((threadIdx.x & 31) == 0) red[threadIdx.x >> 5] = v;
    __syncthreads();
    if (threadIdx.x == 0)
        g_partial[blockIdx.x] = red[0] + red[1] + red[2] + red[3];
}

__global__ void fin2_kernel(float* __restrict__ out, int nblk, int B) {
    __shared__ float red[32];
    float s = 0.f;
    for (int i = threadIdx.x; i < nblk; i += blockDim.x) s += g_partial[i];
    #pragma unroll
    for (int o = 16; o; o >>= 1) s += __shfl_xor_sync(0xffffffffu, s, o);
    if ((threadIdx.x & 31) == 0) red[threadIdx.x >> 5] = s;
    __syncthreads();
    if (threadIdx.x < 32) {
        float v = (threadIdx.x < (blockDim.x >> 5)) ? red[threadIdx.x] : 0.f;
        #pragma unroll
        for (int o = 16; o; o >>= 1) v += __shfl_xor_sync(0xffffffffu, v, o);
        if (threadIdx.x == 0) out[0] = v / (float)B;
    }
}

// ============================================================================
extern "C" void kernel_launch(void* const* d_in, const int* in_sizes, int n_in,
                              void* d_out, int out_size) {
    const float* z      = (const float*)d_in[0];
    const float* protos = (const float*)d_in[1];
    const float* margin = (const float*)d_in[2];
    float* out = (float*)d_out;

    const int B = in_sizes[0] / DDIM;   // 32768
    const int C = in_sizes[1] / DDIM;   // 2048

    cudaFuncSetAttribute(min_dist_mma_kernel,
                         cudaFuncAttributeMaxDynamicSharedMemorySize, SMEM_MAIN);

    conv_z_kernel<<<(B + 7) / 8, 256>>>(z, B);
    conv_p_kernel<<<(C + 7) / 8, 256>>>(protos, C);
    min_dist_mma_kernel<<<B / 128, 256, SMEM_MAIN>>>(C);
    fin1_kernel<<<B / 128, 128>>>(margin);
    fin2_kernel<<<1, 256>>>(out, B / 128, B);
}

// round 7
// speedup vs baseline: 2.4308x; 2.4308x over previous
#include <cuda_runtime.h>
#include <cuda_fp8.h>
#include <cstdint>
#include <math.h>

// ============================================================================
// AdaptiveOutlierLoss: mean(relu(margin - min_c d_poincare(z_b, p_c)))
// B=32768, C=2048, D=512. arccosh monotone + (1-|x|^2) row-constant =>
// argmin_c d == argmin_c (x2 + y2 - 2 dot) / (1 - y2).
// FP8 e4m3 warp-MMA (m16n8k32). CTA tile 128m x 256n per stage, warp tile
// 64x64 => 0.25 ldmatrix per MMA (was 0.375) to relieve the SMEM crossbar.
// ============================================================================

#define DDIM 512
#define MAXB 32768
#define MAXC 2048

// ---------------- device scratch ----------------
__device__ __align__(128) unsigned char g_zt[(size_t)MAXB * DDIM];  // fp8 z (x16)
__device__ __align__(128) unsigned char g_pt[(size_t)MAXC * DDIM];  // fp8 protos (x16)
__device__ float  g_x2[MAXB];
__device__ float2 g_pc[MAXC];        // (y2, 1/(1-y2)) per prototype
__device__ float  g_tmin[MAXB];
__device__ float  g_partial[MAXB / 128];

// ---------------- SMEM map ----------------
// A: 8 k-chunks x [128 rows x 80B]   (64 fp8 k = 64B data + 16B pad)
// B: 4 stages  x [256 rows x 80B]
#define SM_A      0
#define SM_B      81920
#define SM_MIN    163840
#define SMEM_MAIN 164352

// ---------------- asm helpers ----------------
__device__ __forceinline__ uint32_t smem_u32(const void* p) {
    uint32_t a;
    asm("{ .reg .u64 t; cvta.to.shared.u64 t, %1; cvt.u32.u64 %0, t; }" : "=r"(a) : "l"(p));
    return a;
}
__device__ __forceinline__ void cp16(uint32_t dst, const void* src) {
    asm volatile("cp.async.cg.shared.global [%0], [%1], 16;" :: "r"(dst), "l"(src) : "memory");
}
__device__ __forceinline__ void cp_commit() {
    asm volatile("cp.async.commit_group;" ::: "memory");
}
template <int N>
__device__ __forceinline__ void cp_wait() {
    asm volatile("cp.async.wait_group %0;" :: "n"(N) : "memory");
}
#define LDSM4(r, addr)                                                           \
    asm volatile("ldmatrix.sync.aligned.m8n8.x4.shared.b16 {%0,%1,%2,%3}, [%4];" \
                 : "=r"((r)[0]), "=r"((r)[1]), "=r"((r)[2]), "=r"((r)[3])        \
                 : "r"(addr))
__device__ __forceinline__ void mma_fp8(float* d, const uint32_t* a,
                                        uint32_t b0, uint32_t b1) {
    asm volatile(
        "mma.sync.aligned.m16n8k32.row.col.f32.e4m3.e4m3.f32 "
        "{%0,%1,%2,%3}, {%4,%5,%6,%7}, {%8,%9}, {%0,%1,%2,%3};"
        : "+f"(d[0]), "+f"(d[1]), "+f"(d[2]), "+f"(d[3])
        : "r"(a[0]), "r"(a[1]), "r"(a[2]), "r"(a[3]), "r"(b0), "r"(b1));
}

// fp32x4 -> 4 packed e4m3 bytes, pre-scaled by 16
__device__ __forceinline__ uint32_t pack4_fp8(float4 v) {
    __nv_fp8x2_storage_t lo =
        __nv_cvt_float2_to_fp8x2(make_float2(v.x * 16.0f, v.y * 16.0f), __NV_SATFINITE, __NV_E4M3);
    __nv_fp8x2_storage_t hi =
        __nv_cvt_float2_to_fp8x2(make_float2(v.z * 16.0f, v.w * 16.0f), __NV_SATFINITE, __NV_E4M3);
    return (uint32_t)lo | ((uint32_t)hi << 16);
}

// ============================================================================
// Conversion: fp32 -> fp8 row-major (scaled x16), fused fp32 squared-norm.
// ============================================================================
__global__ void conv_z_kernel(const float* __restrict__ z, int B) {
    int w    = (blockIdx.x * blockDim.x + threadIdx.x) >> 5;
    int lane = threadIdx.x & 31;
    if (w >= B) return;
    const float* row = z + (size_t)w * DDIM;
    float s = 0.f;
    #pragma unroll
    for (int i = 0; i < 4; i++) {
        int f = i * 32 + lane;
        float4 v = *(const float4*)(row + f * 4);
        s = fmaf(v.x, v.x, fmaf(v.y, v.y, fmaf(v.z, v.z, fmaf(v.w, v.w, s))));
        *(uint32_t*)(g_zt + (size_t)w * DDIM + f * 4) = pack4_fp8(v);
    }
    #pragma unroll
    for (int o = 16; o; o >>= 1) s += __shfl_xor_sync(0xffffffffu, s, o);
    if (lane == 0) g_x2[w] = s;
}

__global__ void conv_p_kernel(const float* __restrict__ p, int C) {
    int w    = (blockIdx.x * blockDim.x + threadIdx.x) >> 5;
    int lane = threadIdx.x & 31;
    if (w >= C) return;
    const float* row = p + (size_t)w * DDIM;
    float s = 0.f;
    #pragma unroll
    for (int i = 0; i < 4; i++) {
        int f = i * 32 + lane;
        float4 v = *(const float4*)(row + f * 4);
        s = fmaf(v.x, v.x, fmaf(v.y, v.y, fmaf(v.z, v.z, fmaf(v.w, v.w, s))));
        *(uint32_t*)(g_pt + (size_t)w * DDIM + f * 4) = pack4_fp8(v);
    }
    #pragma unroll
    for (int o = 16; o; o >>= 1) s += __shfl_xor_sync(0xffffffffu, s, o);
    if (lane == 0) g_pc[w] = make_float2(s, 1.0f / (1.0f - s));
}

// ============================================================================
// Main kernel: 1 CTA per 128 z-rows. A (128x512 fp8) resident at pitch 80
// (ldmatrix conflict-free). Stage = 256 protos x 64 k (20KB), 4-stage
// cp.async pipeline. 8 warps as 2(m) x 4(n); warp tile 64m x 64n.
// ============================================================================
__global__ void __launch_bounds__(256, 1)
min_dist_mma_kernel(int C) {
    extern __shared__ char smem[];
    const uint32_t sb   = smem_u32(smem);
    const int tid  = threadIdx.x;
    const int lane = tid & 31;
    const int wid  = tid >> 5;
    const int wm   = wid & 1;     // m block of 64
    const int wn   = wid >> 1;    // n block of 64
    const int mb   = blockIdx.x;
    const int NB2  = C >> 8;      // 256-proto super-blocks (8)
    const int NQ   = NB2 * 8;     // stages (64 k each) = 64

    int* sMin = (int*)(smem + SM_MIN);
    if (tid < 128) sMin[tid] = 0x7F800000;

    // ---- prologue: A (whole 128x512B slice) + first 3 B stages ----
    {
        const char* abase = (const char*)g_zt + (size_t)mb * 65536;
        #pragma unroll 4
        for (int t = 0; t < 16; t++) {
            int i = tid + t * 256;          // 4096 16B chunks
            int r = i >> 5;                 // row (32 chunks per row)
            int j = i & 31;                 // chunk within row
            cp16(sb + SM_A + (j >> 2) * 10240 + r * 80 + (j & 3) * 16,
                 abase + r * 512 + j * 16);
        }
    }
    auto load_B = [&](int s, int q) {
        int nb2 = q >> 3, kc = q & 7;
        const char* bbase = (const char*)g_pt + (size_t)nb2 * 131072 + kc * 64;
        #pragma unroll
        for (int t = 0; t < 4; t++) {
            int i = tid + t * 256;          // 1024 chunks (256 rows x 4)
            int r = i >> 2, slot = i & 3;
            cp16(sb + SM_B + s * 20480 + r * 80 + slot * 16,
                 bbase + r * 512 + slot * 16);
        }
    };
    load_B(0, 0); cp_commit();              // group0 = A + B0
    load_B(1, 1); cp_commit();
    load_B(2, 2); cp_commit();

    // ---- per-thread constants ----
    const int g = lane >> 2;
    float x2r[8];
    #pragma unroll
    for (int mt = 0; mt < 4; mt++) {
        int r0 = mb * 128 + wm * 64 + mt * 16 + g;
        x2r[mt * 2]     = g_x2[r0];
        x2r[mt * 2 + 1] = g_x2[r0 + 8];
    }
    float rm[8];
    #pragma unroll
    for (int i = 0; i < 8; i++) rm[i] = __int_as_float(0x7F800000);

    float acc[4][8][4];   // mt x nt(8 over 64 n) x frag
    #pragma unroll
    for (int mt = 0; mt < 4; mt++)
        #pragma unroll
        for (int nt = 0; nt < 8; nt++)
            #pragma unroll
            for (int k = 0; k < 4; k++) acc[mt][nt][k] = 0.f;

    const uint32_t aoff = sb + SM_A + (wm * 64 + (lane & 15)) * 80 + (lane >> 4) * 16;
    const uint32_t boff = sb + SM_B + (wn * 64 + (lane & 15)) * 80 + (lane >> 4) * 16;

    #pragma unroll 1
    for (int q = 0; q < NQ; q++) {
        const int s   = q & 3;
        const int kc  = q & 7;
        const int nb2 = q >> 3;
        const int rem = NQ - 1 - q;
        if (rem >= 2)      cp_wait<2>();
        else if (rem == 1) cp_wait<1>();
        else               cp_wait<0>();
        __syncthreads();
        if (q + 3 < NQ) { load_B((q + 3) & 3, q + 3); cp_commit(); }

        // per-ks fragment load keeps register liveness low
        #pragma unroll
        for (int ks = 0; ks < 2; ks++) {
            uint32_t afr[4][4];
            uint32_t bfr[4][4];
            #pragma unroll
            for (int mt = 0; mt < 4; mt++)
                LDSM4(afr[mt], aoff + kc * 10240 + mt * 1280 + ks * 32);
            #pragma unroll
            for (int p = 0; p < 4; p++)
                LDSM4(bfr[p], boff + s * 20480 + p * 1280 + ks * 32);

            #pragma unroll
            for (int mt = 0; mt < 4; mt++)
                #pragma unroll
                for (int nt = 0; nt < 8; nt++) {
                    int p = nt >> 1, sd = nt & 1;
                    mma_fp8(acc[mt][nt], afr[mt], bfr[p][sd], bfr[p][sd + 2]);
                }
        }

        if (kc == 7) {
            // epilogue for this 256-proto super-block: acc = 256*dot
            const int colbase = nb2 * 256 + wn * 64 + (lane & 3) * 2;
            #pragma unroll
            for (int nt = 0; nt < 8; nt++) {
                float2 pa = __ldg(&g_pc[colbase + nt * 8]);
                float2 pb = __ldg(&g_pc[colbase + nt * 8 + 1]);
                #pragma unroll
                for (int mt = 0; mt < 4; mt++) {
                    float v00 = fmaf(-0.0078125f, acc[mt][nt][0], x2r[mt*2]   + pa.x) * pa.y;
                    float v01 = fmaf(-0.0078125f, acc[mt][nt][1], x2r[mt*2]   + pb.x) * pb.y;
                    float v10 = fmaf(-0.0078125f, acc[mt][nt][2], x2r[mt*2+1] + pa.x) * pa.y;
                    float v11 = fmaf(-0.0078125f, acc[mt][nt][3], x2r[mt*2+1] + pb.x) * pb.y;
                    rm[mt*2]   = fminf(rm[mt*2],   fminf(v00, v01));
                    rm[mt*2+1] = fminf(rm[mt*2+1], fminf(v10, v11));
                    acc[mt][nt][0] = 0.f; acc[mt][nt][1] = 0.f;
                    acc[mt][nt][2] = 0.f; acc[mt][nt][3] = 0.f;
                }
            }
        }
    }

    // ---- cross-warp min + writeback (values >= 0 => int-bit order) ----
    __syncthreads();
    #pragma unroll
    for (int mt = 0; mt < 4; mt++) {
        atomicMin(&sMin[wm * 64 + mt * 16 + g],     __float_as_int(rm[mt*2]));
        atomicMin(&sMin[wm * 64 + mt * 16 + g + 8], __float_as_int(rm[mt*2+1]));
    }
    __syncthreads();
    if (tid < 128) g_tmin[mb * 128 + tid] = __int_as_float(sMin[tid]);
}

// ============================================================================
// Finalize: deterministic two-stage reduction.
// ============================================================================
__global__ void fin1_kernel(const float* __restrict__ margin_p) {
    __shared__ float red[4];
    const int r = blockIdx.x * 128 + threadIdx.x;
    const float margin = *margin_p;
    float t   = g_tmin[r];
    float x2  = g_x2[r];
    float arg = fmaxf(1.0f + 2.0f * t / (1.0f - x2), 1.0f + 1e-7f);
    float v   = fmaxf(margin - acoshf(arg), 0.0f);
    #pragma unroll
    for (int o = 16; o; o >>= 1) v += __shfl_xor_sync(0xffffffffu, v, o);
    if ((threadIdx.x & 31) == 0) red[threadIdx.x >> 5] = v;
    __syncthreads();
    if (threadIdx.x == 0)
        g_partial[blockIdx.x] = red[0] + red[1] + red[2] + red[3];
}

__global__ void fin2_kernel(float* __restrict__ out, int nblk, int B) {
    __shared__ float red[32];
    float s = 0.f;
    for (int i = threadIdx.x; i < nblk; i += blockDim.x) s += g_partial[i];
    #pragma unroll
    for (int o = 16; o; o >>= 1) s += __shfl_xor_sync(0xffffffffu, s, o);
    if ((threadIdx.x & 31) == 0) red[threadIdx.x >> 5] = s;
    __syncthreads();
    if (threadIdx.x < 32) {
        float v = (threadIdx.x < (blockDim.x >> 5)) ? red[threadIdx.x] : 0.f;
        #pragma unroll
        for (int o = 16; o; o >>= 1) v += __shfl_xor_sync(0xffffffffu, v, o);
        if (threadIdx.x == 0) out[0] = v / (float)B;
    }
}

// ============================================================================
extern "C" void kernel_launch(void* const* d_in, const int* in_sizes, int n_in,
                              void* d_out, int out_size) {
    const float* z      = (const float*)d_in[0];
    const float* protos = (const float*)d_in[1];
    const float* margin = (const float*)d_in[2];
    float* out = (float*)d_out;

    const int B = in_sizes[0] / DDIM;   // 32768
    const int C = in_sizes[1] / DDIM;   // 2048

    cudaFuncSetAttribute(min_dist_mma_kernel,
                         cudaFuncAttributeMaxDynamicSharedMemorySize, SMEM_MAIN);

    conv_z_kernel<<<(B + 7) / 8, 256>>>(z, B);
    conv_p_kernel<<<(C + 7) / 8, 256>>>(protos, C);
    min_dist_mma_kernel<<<B / 128, 256, SMEM_MAIN>>>(C);
    fin1_kernel<<<B / 128, 128>>>(margin);
    fin2_kernel<<<1, 256>>>(out, B / 128, B);
}

// round 8
// speedup vs baseline: 2.6307x; 1.0822x over previous
#include <cuda_runtime.h>
#include <cuda_fp8.h>
#include <cstdint>
#include <math.h>

// ============================================================================
// AdaptiveOutlierLoss: mean(relu(margin - min_c d_poincare(z_b, p_c)))
// B=32768, C=2048, D=512. arccosh monotone + (1-|x|^2) row-constant =>
// argmin_c d == argmin_c (x2 + y2 - 2 dot) / (1 - y2).
// FP8 e4m3 warp-MMA (m16n8k32), warp tile 64x64. QMMA-rate-bound => recover
// the wave-quantization tax: grid (4 C-splits x 256 M-blocks) = 1024 CTAs of
// T/4 -> 6.92 waves instead of 2.0 full waves of T. Cross-CTA min via global
// ordered-int atomicMin.
// ============================================================================

#define DDIM 512
#define MAXB 32768
#define MAXC 2048

// ---------------- device scratch ----------------
__device__ __align__(128) unsigned char g_zt[(size_t)MAXB * DDIM];  // fp8 z (x16)
__device__ __align__(128) unsigned char g_pt[(size_t)MAXC * DDIM];  // fp8 protos (x16)
__device__ float  g_x2[MAXB];
__device__ float2 g_pc[MAXC];        // (y2, 1/(1-y2)) per prototype
__device__ int    g_tmin_bits[MAXB]; // ordered-int min across C-split CTAs
__device__ float  g_partial[MAXB / 128];

// ---------------- SMEM map ----------------
// A: 8 k-chunks x [128 rows x 80B]   (64 fp8 k = 64B data + 16B pad)
// B: 4 stages  x [256 rows x 80B]
#define SM_A      0
#define SM_B      81920
#define SM_MIN    163840
#define SMEM_MAIN 164352

// ---------------- asm helpers ----------------
__device__ __forceinline__ uint32_t smem_u32(const void* p) {
    uint32_t a;
    asm("{ .reg .u64 t; cvta.to.shared.u64 t, %1; cvt.u32.u64 %0, t; }" : "=r"(a) : "l"(p));
    return a;
}
__device__ __forceinline__ void cp16(uint32_t dst, const void* src) {
    asm volatile("cp.async.cg.shared.global [%0], [%1], 16;" :: "r"(dst), "l"(src) : "memory");
}
__device__ __forceinline__ void cp_commit() {
    asm volatile("cp.async.commit_group;" ::: "memory");
}
template <int N>
__device__ __forceinline__ void cp_wait() {
    asm volatile("cp.async.wait_group %0;" :: "n"(N) : "memory");
}
#define LDSM4(r, addr)                                                           \
    asm volatile("ldmatrix.sync.aligned.m8n8.x4.shared.b16 {%0,%1,%2,%3}, [%4];" \
                 : "=r"((r)[0]), "=r"((r)[1]), "=r"((r)[2]), "=r"((r)[3])        \
                 : "r"(addr))
__device__ __forceinline__ void mma_fp8(float* d, const uint32_t* a,
                                        uint32_t b0, uint32_t b1) {
    asm volatile(
        "mma.sync.aligned.m16n8k32.row.col.f32.e4m3.e4m3.f32 "
        "{%0,%1,%2,%3}, {%4,%5,%6,%7}, {%8,%9}, {%0,%1,%2,%3};"
        : "+f"(d[0]), "+f"(d[1]), "+f"(d[2]), "+f"(d[3])
        : "r"(a[0]), "r"(a[1]), "r"(a[2]), "r"(a[3]), "r"(b0), "r"(b1));
}

// fp32x4 -> 4 packed e4m3 bytes, pre-scaled by 16
__device__ __forceinline__ uint32_t pack4_fp8(float4 v) {
    __nv_fp8x2_storage_t lo =
        __nv_cvt_float2_to_fp8x2(make_float2(v.x * 16.0f, v.y * 16.0f), __NV_SATFINITE, __NV_E4M3);
    __nv_fp8x2_storage_t hi =
        __nv_cvt_float2_to_fp8x2(make_float2(v.z * 16.0f, v.w * 16.0f), __NV_SATFINITE, __NV_E4M3);
    return (uint32_t)lo | ((uint32_t)hi << 16);
}

// ============================================================================
// Conversion: fp32 -> fp8 row-major (scaled x16), fused fp32 squared-norm and
// g_tmin init. One warp per row.
// ============================================================================
__global__ void conv_z_kernel(const float* __restrict__ z, int B) {
    int w    = (blockIdx.x * blockDim.x + threadIdx.x) >> 5;
    int lane = threadIdx.x & 31;
    if (w >= B) return;
    const float* row = z + (size_t)w * DDIM;
    float s = 0.f;
    #pragma unroll
    for (int i = 0; i < 4; i++) {
        int f = i * 32 + lane;
        float4 v = *(const float4*)(row + f * 4);
        s = fmaf(v.x, v.x, fmaf(v.y, v.y, fmaf(v.z, v.z, fmaf(v.w, v.w, s))));
        *(uint32_t*)(g_zt + (size_t)w * DDIM + f * 4) = pack4_fp8(v);
    }
    #pragma unroll
    for (int o = 16; o; o >>= 1) s += __shfl_xor_sync(0xffffffffu, s, o);
    if (lane == 0) {
        g_x2[w] = s;
        g_tmin_bits[w] = 0x7F800000;   // +inf
    }
}

__global__ void conv_p_kernel(const float* __restrict__ p, int C) {
    int w    = (blockIdx.x * blockDim.x + threadIdx.x) >> 5;
    int lane = threadIdx.x & 31;
    if (w >= C) return;
    const float* row = p + (size_t)w * DDIM;
    float s = 0.f;
    #pragma unroll
    for (int i = 0; i < 4; i++) {
        int f = i * 32 + lane;
        float4 v = *(const float4*)(row + f * 4);
        s = fmaf(v.x, v.x, fmaf(v.y, v.y, fmaf(v.z, v.z, fmaf(v.w, v.w, s))));
        *(uint32_t*)(g_pt + (size_t)w * DDIM + f * 4) = pack4_fp8(v);
    }
    #pragma unroll
    for (int o = 16; o; o >>= 1) s += __shfl_xor_sync(0xffffffffu, s, o);
    if (lane == 0) g_pc[w] = make_float2(s, 1.0f / (1.0f - s));
}

// ============================================================================
// Main kernel: grid (4, B/128). CTA (cq, mb) handles 128 z-rows x 512 protos
// (quarter of C). A (128x512 fp8) resident at pitch 80 (ldmatrix conflict-
// free). Stage = 256 protos x 64 k (20KB), 4-stage cp.async pipeline.
// 8 warps as 2(m) x 4(n); warp tile 64m x 64n. Cross-CTA combine via global
// ordered-int atomicMin (all candidate values >= 0).
// ============================================================================
__global__ void __launch_bounds__(256, 1)
min_dist_mma_kernel(int C) {
    extern __shared__ char smem[];
    const uint32_t sb   = smem_u32(smem);
    const int tid  = threadIdx.x;
    const int lane = tid & 31;
    const int wid  = tid >> 5;
    const int wm   = wid & 1;     // m block of 64
    const int wn   = wid >> 1;    // n block of 64
    const int cq   = blockIdx.x;  // C quarter
    const int mb   = blockIdx.y;
    const int NQ   = 16;          // 2 super-blocks x 8 k-chunks

    int* sMin = (int*)(smem + SM_MIN);
    if (tid < 128) sMin[tid] = 0x7F800000;

    // ---- prologue: A (whole 128x512B slice) + first 3 B stages ----
    {
        const char* abase = (const char*)g_zt + (size_t)mb * 65536;
        #pragma unroll 4
        for (int t = 0; t < 16; t++) {
            int i = tid + t * 256;          // 4096 16B chunks
            int r = i >> 5;                 // row (32 chunks per row)
            int j = i & 31;                 // chunk within row
            cp16(sb + SM_A + (j >> 2) * 10240 + r * 80 + (j & 3) * 16,
                 abase + r * 512 + j * 16);
        }
    }
    auto load_B = [&](int s, int q) {
        int nb2 = cq * 2 + (q >> 3);        // global 256-proto super-block
        int kc  = q & 7;
        const char* bbase = (const char*)g_pt + (size_t)nb2 * 131072 + kc * 64;
        #pragma unroll
        for (int t = 0; t < 4; t++) {
            int i = tid + t * 256;          // 1024 chunks (256 rows x 4)
            int r = i >> 2, slot = i & 3;
            cp16(sb + SM_B + s * 20480 + r * 80 + slot * 16,
                 bbase + r * 512 + slot * 16);
        }
    };
    load_B(0, 0); cp_commit();              // group0 = A + B0
    load_B(1, 1); cp_commit();
    load_B(2, 2); cp_commit();

    // ---- per-thread constants ----
    const int g = lane >> 2;
    float x2r[8];
    #pragma unroll
    for (int mt = 0; mt < 4; mt++) {
        int r0 = mb * 128 + wm * 64 + mt * 16 + g;
        x2r[mt * 2]     = g_x2[r0];
        x2r[mt * 2 + 1] = g_x2[r0 + 8];
    }
    float rm[8];
    #pragma unroll
    for (int i = 0; i < 8; i++) rm[i] = __int_as_float(0x7F800000);

    float acc[4][8][4];   // mt x nt(8 over 64 n) x frag
    #pragma unroll
    for (int mt = 0; mt < 4; mt++)
        #pragma unroll
        for (int nt = 0; nt < 8; nt++)
            #pragma unroll
            for (int k = 0; k < 4; k++) acc[mt][nt][k] = 0.f;

    const uint32_t aoff = sb + SM_A + (wm * 64 + (lane & 15)) * 80 + (lane >> 4) * 16;
    const uint32_t boff = sb + SM_B + (wn * 64 + (lane & 15)) * 80 + (lane >> 4) * 16;

    #pragma unroll 1
    for (int q = 0; q < NQ; q++) {
        const int s   = q & 3;
        const int kc  = q & 7;
        const int rem = NQ - 1 - q;
        if (rem >= 2)      cp_wait<2>();
        else if (rem == 1) cp_wait<1>();
        else               cp_wait<0>();
        __syncthreads();
        if (q + 3 < NQ) { load_B((q + 3) & 3, q + 3); cp_commit(); }

        #pragma unroll
        for (int ks = 0; ks < 2; ks++) {
            uint32_t afr[4][4];
            uint32_t bfr[4][4];
            #pragma unroll
            for (int mt = 0; mt < 4; mt++)
                LDSM4(afr[mt], aoff + kc * 10240 + mt * 1280 + ks * 32);
            #pragma unroll
            for (int p = 0; p < 4; p++)
                LDSM4(bfr[p], boff + s * 20480 + p * 1280 + ks * 32);

            #pragma unroll
            for (int mt = 0; mt < 4; mt++)
                #pragma unroll
                for (int nt = 0; nt < 8; nt++) {
                    int p = nt >> 1, sd = nt & 1;
                    mma_fp8(acc[mt][nt], afr[mt], bfr[p][sd], bfr[p][sd + 2]);
                }
        }

        if (kc == 7) {
            // epilogue for this 256-proto super-block: acc = 256*dot
            const int nb2 = cq * 2 + (q >> 3);
            const int colbase = nb2 * 256 + wn * 64 + (lane & 3) * 2;
            #pragma unroll
            for (int nt = 0; nt < 8; nt++) {
                float2 pa = __ldg(&g_pc[colbase + nt * 8]);
                float2 pb = __ldg(&g_pc[colbase + nt * 8 + 1]);
                #pragma unroll
                for (int mt = 0; mt < 4; mt++) {
                    float v00 = fmaf(-0.0078125f, acc[mt][nt][0], x2r[mt*2]   + pa.x) * pa.y;
                    float v01 = fmaf(-0.0078125f, acc[mt][nt][1], x2r[mt*2]   + pb.x) * pb.y;
                    float v10 = fmaf(-0.0078125f, acc[mt][nt][2], x2r[mt*2+1] + pa.x) * pa.y;
                    float v11 = fmaf(-0.0078125f, acc[mt][nt][3], x2r[mt*2+1] + pb.x) * pb.y;
                    rm[mt*2]   = fminf(rm[mt*2],   fminf(v00, v01));
                    rm[mt*2+1] = fminf(rm[mt*2+1], fminf(v10, v11));
                    acc[mt][nt][0] = 0.f; acc[mt][nt][1] = 0.f;
                    acc[mt][nt][2] = 0.f; acc[mt][nt][3] = 0.f;
                }
            }
        }
    }

    // ---- cross-warp min + global combine (values >= 0 => int-bit order) ----
    __syncthreads();
    #pragma unroll
    for (int mt = 0; mt < 4; mt++) {
        atomicMin(&sMin[wm * 64 + mt * 16 + g],     __float_as_int(rm[mt*2]));
        atomicMin(&sMin[wm * 64 + mt * 16 + g + 8], __float_as_int(rm[mt*2+1]));
    }
    __syncthreads();
    if (tid < 128) atomicMin(&g_tmin_bits[mb * 128 + tid], sMin[tid]);
}

// ============================================================================
// Finalize: deterministic two-stage reduction.
// ============================================================================
__global__ void fin1_kernel(const float* __restrict__ margin_p) {
    __shared__ float red[4];
    const int r = blockIdx.x * 128 + threadIdx.x;
    const float margin = *margin_p;
    float t   = __int_as_float(g_tmin_bits[r]);
    float x2  = g_x2[r];
    float arg = fmaxf(1.0f + 2.0f * t / (1.0f - x2), 1.0f + 1e-7f);
    float v   = fmaxf(margin - acoshf(arg), 0.0f);
    #pragma unroll
    for (int o = 16; o; o >>= 1) v += __shfl_xor_sync(0xffffffffu, v, o);
    if ((threadIdx.x & 31) == 0) red[threadIdx.x >> 5] = v;
    __syncthreads();
    if (threadIdx.x == 0)
        g_partial[blockIdx.x] = red[0] + red[1] + red[2] + red[3];
}

__global__ void fin2_kernel(float* __restrict__ out, int nblk, int B) {
    __shared__ float red[32];
    float s = 0.f;
    for (int i = threadIdx.x; i < nblk; i += blockDim.x) s += g_partial[i];
    #pragma unroll
    for (int o = 16; o; o >>= 1) s += __shfl_xor_sync(0xffffffffu, s, o);
    if ((threadIdx.x & 31) == 0) red[threadIdx.x >> 5] = s;
    __syncthreads();
    if (threadIdx.x < 32) {
        float v = (threadIdx.x < (blockDim.x >> 5)) ? red[threadIdx.x] : 0.f;
        #pragma unroll
        for (int o = 16; o; o >>= 1) v += __shfl_xor_sync(0xffffffffu, v, o);
        if (threadIdx.x == 0) out[0] = v / (float)B;
    }
}

// ============================================================================
extern "C" void kernel_launch(void* const* d_in, const int* in_sizes, int n_in,
                              void* d_out, int out_size) {
    const float* z      = (const float*)d_in[0];
    const float* protos = (const float*)d_in[1];
    const float* margin = (const float*)d_in[2];
    float* out = (float*)d_out;

    const int B = in_sizes[0] / DDIM;   // 32768
    const int C = in_sizes[1] / DDIM;   // 2048

    cudaFuncSetAttribute(min_dist_mma_kernel,
                         cudaFuncAttributeMaxDynamicSharedMemorySize, SMEM_MAIN);

    conv_z_kernel<<<(B + 7) / 8, 256>>>(z, B);
    conv_p_kernel<<<(C + 7) / 8, 256>>>(protos, C);
    {
        dim3 grid(4, B / 128);          // 4 C-splits x 256 M-blocks
        min_dist_mma_kernel<<<grid, 256, SMEM_MAIN>>>(C);
    }
    fin1_kernel<<<B / 128, 128>>>(margin);
    fin2_kernel<<<1, 256>>>(out, B / 128, B);
}

// round 9
// speedup vs baseline: 2.7524x; 1.0462x over previous
#include <cuda_runtime.h>
#include <cuda_fp8.h>
#include <cuda_fp16.h>
#include <cstdint>
#include <math.h>

// ============================================================================
// AdaptiveOutlierLoss: mean(relu(margin - min_c d_poincare(z_b, p_c)))
// B=32768, C=2048, D=512. arccosh monotone + (1-|x|^2) row-constant =>
// argmin_c d == argmin_c (x2 + y2 - 2 dot) / (1 - y2).
// FP8 e4m3 warp-MMA (m16n8k32) with **f16 accumulators** (testing whether the
// fallback pipe runs f16-accum MMA at 2x the f32-accum rate, as on prior
// de-rated pipes). Warp tile 64x64, grid (4 C-splits x 256 M-blocks).
// ============================================================================

#define DDIM 512
#define MAXB 32768
#define MAXC 2048

// ---------------- device scratch ----------------
__device__ __align__(128) unsigned char g_zt[(size_t)MAXB * DDIM];  // fp8 z (x16)
__device__ __align__(128) unsigned char g_pt[(size_t)MAXC * DDIM];  // fp8 protos (x16)
__device__ float  g_x2[MAXB];
__device__ float2 g_pc[MAXC];        // (y2, 1/(1-y2)) per prototype
__device__ int    g_tmin_bits[MAXB]; // ordered-int min across C-split CTAs
__device__ float  g_partial[MAXB / 128];

// ---------------- SMEM map ----------------
#define SM_A      0
#define SM_B      81920
#define SM_MIN    163840
#define SMEM_MAIN 164352

// ---------------- asm helpers ----------------
__device__ __forceinline__ uint32_t smem_u32(const void* p) {
    uint32_t a;
    asm("{ .reg .u64 t; cvta.to.shared.u64 t, %1; cvt.u32.u64 %0, t; }" : "=r"(a) : "l"(p));
    return a;
}
__device__ __forceinline__ void cp16(uint32_t dst, const void* src) {
    asm volatile("cp.async.cg.shared.global [%0], [%1], 16;" :: "r"(dst), "l"(src) : "memory");
}
__device__ __forceinline__ void cp_commit() {
    asm volatile("cp.async.commit_group;" ::: "memory");
}
template <int N>
__device__ __forceinline__ void cp_wait() {
    asm volatile("cp.async.wait_group %0;" :: "n"(N) : "memory");
}
#define LDSM4(r, addr)                                                           \
    asm volatile("ldmatrix.sync.aligned.m8n8.x4.shared.b16 {%0,%1,%2,%3}, [%4];" \
                 : "=r"((r)[0]), "=r"((r)[1]), "=r"((r)[2]), "=r"((r)[3])        \
                 : "r"(addr))
// fp8 e4m3 MMA with fp16 accumulators: D(2 x f16x2) = A*B + C
__device__ __forceinline__ void mma_fp8_h(uint32_t* d, const uint32_t* a,
                                          uint32_t b0, uint32_t b1) {
    asm volatile(
        "mma.sync.aligned.m16n8k32.row.col.f16.e4m3.e4m3.f16 "
        "{%0,%1}, {%2,%3,%4,%5}, {%6,%7}, {%0,%1};"
        : "+r"(d[0]), "+r"(d[1])
        : "r"(a[0]), "r"(a[1]), "r"(a[2]), "r"(a[3]), "r"(b0), "r"(b1));
}

// fp32x4 -> 4 packed e4m3 bytes, pre-scaled by 16
__device__ __forceinline__ uint32_t pack4_fp8(float4 v) {
    __nv_fp8x2_storage_t lo =
        __nv_cvt_float2_to_fp8x2(make_float2(v.x * 16.0f, v.y * 16.0f), __NV_SATFINITE, __NV_E4M3);
    __nv_fp8x2_storage_t hi =
        __nv_cvt_float2_to_fp8x2(make_float2(v.z * 16.0f, v.w * 16.0f), __NV_SATFINITE, __NV_E4M3);
    return (uint32_t)lo | ((uint32_t)hi << 16);
}

// ============================================================================
// Conversion: fp32 -> fp8 row-major (scaled x16), fused fp32 squared-norm and
// g_tmin init. One warp per row.
// ============================================================================
__global__ void conv_z_kernel(const float* __restrict__ z, int B) {
    int w    = (blockIdx.x * blockDim.x + threadIdx.x) >> 5;
    int lane = threadIdx.x & 31;
    if (w >= B) return;
    const float* row = z + (size_t)w * DDIM;
    float s = 0.f;
    #pragma unroll
    for (int i = 0; i < 4; i++) {
        int f = i * 32 + lane;
        float4 v = *(const float4*)(row + f * 4);
        s = fmaf(v.x, v.x, fmaf(v.y, v.y, fmaf(v.z, v.z, fmaf(v.w, v.w, s))));
        *(uint32_t*)(g_zt + (size_t)w * DDIM + f * 4) = pack4_fp8(v);
    }
    #pragma unroll
    for (int o = 16; o; o >>= 1) s += __shfl_xor_sync(0xffffffffu, s, o);
    if (lane == 0) {
        g_x2[w] = s;
        g_tmin_bits[w] = 0x7F800000;   // +inf
    }
}

__global__ void conv_p_kernel(const float* __restrict__ p, int C) {
    int w    = (blockIdx.x * blockDim.x + threadIdx.x) >> 5;
    int lane = threadIdx.x & 31;
    if (w >= C) return;
    const float* row = p + (size_t)w * DDIM;
    float s = 0.f;
    #pragma unroll
    for (int i = 0; i < 4; i++) {
        int f = i * 32 + lane;
        float4 v = *(const float4*)(row + f * 4);
        s = fmaf(v.x, v.x, fmaf(v.y, v.y, fmaf(v.z, v.z, fmaf(v.w, v.w, s))));
        *(uint32_t*)(g_pt + (size_t)w * DDIM + f * 4) = pack4_fp8(v);
    }
    #pragma unroll
    for (int o = 16; o; o >>= 1) s += __shfl_xor_sync(0xffffffffu, s, o);
    if (lane == 0) g_pc[w] = make_float2(s, 1.0f / (1.0f - s));
}

// ============================================================================
// Main kernel: grid (4, B/128). CTA (cq, mb) = 128 z-rows x 512 protos.
// A resident at pitch 80 (ldmatrix conflict-free). Stage = 256 protos x 64 k
// (20KB), 4-stage cp.async pipeline. 8 warps as 2(m) x 4(n), warp tile 64x64.
// f16 accumulators (2 regs per m16n8 fragment).
// ============================================================================
__global__ void __launch_bounds__(256, 1)
min_dist_mma_kernel(int C) {
    extern __shared__ char smem[];
    const uint32_t sb   = smem_u32(smem);
    const int tid  = threadIdx.x;
    const int lane = tid & 31;
    const int wid  = tid >> 5;
    const int wm   = wid & 1;     // m block of 64
    const int wn   = wid >> 1;    // n block of 64
    const int cq   = blockIdx.x;  // C quarter
    const int mb   = blockIdx.y;
    const int NQ   = 16;          // 2 super-blocks x 8 k-chunks

    int* sMin = (int*)(smem + SM_MIN);
    if (tid < 128) sMin[tid] = 0x7F800000;

    // ---- prologue: A (whole 128x512B slice) + first 3 B stages ----
    {
        const char* abase = (const char*)g_zt + (size_t)mb * 65536;
        #pragma unroll 4
        for (int t = 0; t < 16; t++) {
            int i = tid + t * 256;          // 4096 16B chunks
            int r = i >> 5;
            int j = i & 31;
            cp16(sb + SM_A + (j >> 2) * 10240 + r * 80 + (j & 3) * 16,
                 abase + r * 512 + j * 16);
        }
    }
    auto load_B = [&](int s, int q) {
        int nb2 = cq * 2 + (q >> 3);        // global 256-proto super-block
        int kc  = q & 7;
        const char* bbase = (const char*)g_pt + (size_t)nb2 * 131072 + kc * 64;
        #pragma unroll
        for (int t = 0; t < 4; t++) {
            int i = tid + t * 256;          // 1024 chunks (256 rows x 4)
            int r = i >> 2, slot = i & 3;
            cp16(sb + SM_B + s * 20480 + r * 80 + slot * 16,
                 bbase + r * 512 + slot * 16);
        }
    };
    load_B(0, 0); cp_commit();              // group0 = A + B0
    load_B(1, 1); cp_commit();
    load_B(2, 2); cp_commit();

    // ---- per-thread constants ----
    const int g = lane >> 2;
    float x2r[8];
    #pragma unroll
    for (int mt = 0; mt < 4; mt++) {
        int r0 = mb * 128 + wm * 64 + mt * 16 + g;
        x2r[mt * 2]     = g_x2[r0];
        x2r[mt * 2 + 1] = g_x2[r0 + 8];
    }
    float rm[8];
    #pragma unroll
    for (int i = 0; i < 8; i++) rm[i] = __int_as_float(0x7F800000);

    uint32_t acc[4][8][2];   // mt x nt x 2 packed f16x2 regs
    #pragma unroll
    for (int mt = 0; mt < 4; mt++)
        #pragma unroll
        for (int nt = 0; nt < 8; nt++) { acc[mt][nt][0] = 0u; acc[mt][nt][1] = 0u; }

    const uint32_t aoff = sb + SM_A + (wm * 64 + (lane & 15)) * 80 + (lane >> 4) * 16;
    const uint32_t boff = sb + SM_B + (wn * 64 + (lane & 15)) * 80 + (lane >> 4) * 16;

    #pragma unroll 1
    for (int q = 0; q < NQ; q++) {
        const int s   = q & 3;
        const int kc  = q & 7;
        const int rem = NQ - 1 - q;
        if (rem >= 2)      cp_wait<2>();
        else if (rem == 1) cp_wait<1>();
        else               cp_wait<0>();
        __syncthreads();
        if (q + 3 < NQ) { load_B((q + 3) & 3, q + 3); cp_commit(); }

        #pragma unroll
        for (int ks = 0; ks < 2; ks++) {
            uint32_t afr[4][4];
            uint32_t bfr[4][4];
            #pragma unroll
            for (int mt = 0; mt < 4; mt++)
                LDSM4(afr[mt], aoff + kc * 10240 + mt * 1280 + ks * 32);
            #pragma unroll
            for (int p = 0; p < 4; p++)
                LDSM4(bfr[p], boff + s * 20480 + p * 1280 + ks * 32);

            #pragma unroll
            for (int mt = 0; mt < 4; mt++)
                #pragma unroll
                for (int nt = 0; nt < 8; nt++) {
                    int p = nt >> 1, sd = nt & 1;
                    mma_fp8_h(acc[mt][nt], afr[mt], bfr[p][sd], bfr[p][sd + 2]);
                }
        }

        if (kc == 7) {
            // epilogue for this 256-proto super-block: acc = f16(256*dot)
            const int nb2 = cq * 2 + (q >> 3);
            const int colbase = nb2 * 256 + wn * 64 + (lane & 3) * 2;
            #pragma unroll
            for (int nt = 0; nt < 8; nt++) {
                float2 pa = __ldg(&g_pc[colbase + nt * 8]);
                float2 pb = __ldg(&g_pc[colbase + nt * 8 + 1]);
                #pragma unroll
                for (int mt = 0; mt < 4; mt++) {
                    float2 d0 = __half22float2(*(const __half2*)&acc[mt][nt][0]); // row g
                    float2 d1 = __half22float2(*(const __half2*)&acc[mt][nt][1]); // row g+8
                    float v00 = fmaf(-0.0078125f, d0.x, x2r[mt*2]   + pa.x) * pa.y;
                    float v01 = fmaf(-0.0078125f, d0.y, x2r[mt*2]   + pb.x) * pb.y;
                    float v10 = fmaf(-0.0078125f, d1.x, x2r[mt*2+1] + pa.x) * pa.y;
                    float v11 = fmaf(-0.0078125f, d1.y, x2r[mt*2+1] + pb.x) * pb.y;
                    rm[mt*2]   = fminf(rm[mt*2],   fminf(v00, v01));
                    rm[mt*2+1] = fminf(rm[mt*2+1], fminf(v10, v11));
                    acc[mt][nt][0] = 0u; acc[mt][nt][1] = 0u;
                }
            }
        }
    }

    // ---- cross-warp min + global combine (values >= 0 => int-bit order) ----
    __syncthreads();
    #pragma unroll
    for (int mt = 0; mt < 4; mt++) {
        atomicMin(&sMin[wm * 64 + mt * 16 + g],     __float_as_int(rm[mt*2]));
        atomicMin(&sMin[wm * 64 + mt * 16 + g + 8], __float_as_int(rm[mt*2+1]));
    }
    __syncthreads();
    if (tid < 128) atomicMin(&g_tmin_bits[mb * 128 + tid], sMin[tid]);
}

// ============================================================================
// Finalize: deterministic two-stage reduction.
// ============================================================================
__global__ void fin1_kernel(const float* __restrict__ margin_p) {
    __shared__ float red[4];
    const int r = blockIdx.x * 128 + threadIdx.x;
    const float margin = *margin_p;
    float t   = __int_as_float(g_tmin_bits[r]);
    float x2  = g_x2[r];
    float arg = fmaxf(1.0f + 2.0f * t / (1.0f - x2), 1.0f + 1e-7f);
    float v   = fmaxf(margin - acoshf(arg), 0.0f);
    #pragma unroll
    for (int o = 16; o; o >>= 1) v += __shfl_xor_sync(0xffffffffu, v, o);
    if ((threadIdx.x & 31) == 0) red[threadIdx.x >> 5] = v;
    __syncthreads();
    if (threadIdx.x == 0)
        g_partial[blockIdx.x] = red[0] + red[1] + red[2] + red[3];
}

__global__ void fin2_kernel(float* __restrict__ out, int nblk, int B) {
    __shared__ float red[32];
    float s = 0.f;
    for (int i = threadIdx.x; i < nblk; i += blockDim.x) s += g_partial[i];
    #pragma unroll
    for (int o = 16; o; o >>= 1) s += __shfl_xor_sync(0xffffffffu, s, o);
    if ((threadIdx.x & 31) == 0) red[threadIdx.x >> 5] = s;
    __syncthreads();
    if (threadIdx.x < 32) {
        float v = (threadIdx.x < (blockDim.x >> 5)) ? red[threadIdx.x] : 0.f;
        #pragma unroll
        for (int o = 16; o; o >>= 1) v += __shfl_xor_sync(0xffffffffu, v, o);
        if (threadIdx.x == 0) out[0] = v / (float)B;
    }
}

// ============================================================================
extern "C" void kernel_launch(void* const* d_in, const int* in_sizes, int n_in,
                              void* d_out, int out_size) {
    const float* z      = (const float*)d_in[0];
    const float* protos = (const float*)d_in[1];
    const float* margin = (const float*)d_in[2];
    float* out = (float*)d_out;

    const int B = in_sizes[0] / DDIM;   // 32768
    const int C = in_sizes[1] / DDIM;   // 2048

    cudaFuncSetAttribute(min_dist_mma_kernel,
                         cudaFuncAttributeMaxDynamicSharedMemorySize, SMEM_MAIN);

    conv_z_kernel<<<(B + 7) / 8, 256>>>(z, B);
    conv_p_kernel<<<(C + 7) / 8, 256>>>(protos, C);
    {
        dim3 grid(4, B / 128);          // 4 C-splits x 256 M-blocks
        min_dist_mma_kernel<<<grid, 256, SMEM_MAIN>>>(C);
    }
    fin1_kernel<<<B / 128, 128>>>(margin);
    fin2_kernel<<<1, 256>>>(out, B / 128, B);
}